// round 2
// baseline (speedup 1.0000x reference)
#include <cuda_runtime.h>

#define F_IN 128          // NBR_IN == AGENT_IN == HID == 128
#define HID 128
#define NBR_OUT 8
#define OUT_COLS 264      // MAX_NBRS*NBR_OUT + AGENT_OUT
#define MAXN 50176        // >= 50000, padded

// Scratch (no allocation allowed): projected node features
__device__ float g_Pn[(size_t)MAXN * HID];   // x_nbr  @ W1[:128]
__device__ float g_Pa[(size_t)MAXN * HID];   // x_agent@ W1[128:] + b1
__device__ int   g_idx64;                    // 1 if edge indices are int64

// ---------------------------------------------------------------------------
// Detect index dtype from edge_slot pattern: int32 words -> 0,1,2,...
// int64 words (little-endian, values < 2^31) -> 0,0,1,0,2,0,...
__global__ void detect_idx_kernel(const int* __restrict__ eslot_words) {
    g_idx64 = (eslot_words[1] != 1) ? 1 : 0;
}

// ---------------------------------------------------------------------------
__global__ void zero_out_kernel(float* __restrict__ out, int n) {
    int n4 = n >> 2;
    float4* o4 = (float4*)out;
    float4 z = make_float4(0.f, 0.f, 0.f, 0.f);
    for (int i = blockIdx.x * blockDim.x + threadIdx.x; i < n4;
         i += gridDim.x * blockDim.x)
        o4[i] = z;
    // tail (OUT_COLS is a multiple of 4, so normally empty)
    if (blockIdx.x == 0 && threadIdx.x == 0)
        for (int i = n4 * 4; i < n; i++) out[i] = 0.f;
}

// ---------------------------------------------------------------------------
// P[N,128] = X[N,128] @ W[128,128] (+ bias).  dst_sel: 0 -> g_Pn, 1 -> g_Pa.
// Block: 256 threads, 64 rows x 128 cols. W fully staged in smem.
__global__ __launch_bounds__(256) void gemm_x128(
    const float* __restrict__ X, const float* __restrict__ W,
    const float* __restrict__ bias, int dst_sel, int N)
{
    extern __shared__ float sm[];
    float* ws = sm;                 // [128][128]
    float* xs = sm + 128 * 128;     // [64][132]  (pad 4 to kill bank conflicts)
    const int t = threadIdx.x;
    const int row0 = blockIdx.x * 64;
    float* __restrict__ P = dst_sel ? g_Pa : g_Pn;

    // stage W (4096 float4)
    {
        const float4* W4 = (const float4*)W;
        float4* ws4 = (float4*)ws;
#pragma unroll
        for (int i = 0; i < 16; i++) ws4[t + 256 * i] = W4[t + 256 * i];
    }
    // stage X tile (64 rows x 32 float4), zero-pad OOB rows
    for (int i = t; i < 64 * 32; i += 256) {
        int r = i >> 5, c4 = i & 31;
        float4 v = make_float4(0.f, 0.f, 0.f, 0.f);
        int gr = row0 + r;
        if (gr < N) v = ((const float4*)X)[(size_t)gr * 32 + c4];
        float* xr = xs + r * 132 + c4 * 4;
        xr[0] = v.x; xr[1] = v.y; xr[2] = v.z; xr[3] = v.w;
    }
    __syncthreads();

    const int c  = (t & 31) * 4;    // output col group
    const int r0 = (t >> 5) * 8;    // output row group
    float acc[8][4];
#pragma unroll
    for (int i = 0; i < 8; i++) {
#pragma unroll
        for (int j = 0; j < 4; j++)
            acc[i][j] = bias ? bias[c + j] : 0.f;
    }

#pragma unroll 8
    for (int k = 0; k < 128; k++) {
        float4 b = *(const float4*)(ws + k * 128 + c);
#pragma unroll
        for (int i = 0; i < 8; i++) {
            float a = xs[(r0 + i) * 132 + k];
            acc[i][0] += a * b.x;
            acc[i][1] += a * b.y;
            acc[i][2] += a * b.z;
            acc[i][3] += a * b.w;
        }
    }

#pragma unroll
    for (int i = 0; i < 8; i++) {
        int gr = row0 + r0 + i;
        if (gr < N)
            *(float4*)(P + (size_t)gr * 128 + c) =
                make_float4(acc[i][0], acc[i][1], acc[i][2], acc[i][3]);
    }
}

// ---------------------------------------------------------------------------
// own_score = x_agent @ Wa + ba  ->  out[:, 256:264]
__global__ void own_kernel(const float* __restrict__ xa,
                           const float* __restrict__ Wa,
                           const float* __restrict__ ba,
                           float* __restrict__ out, int N)
{
    __shared__ float ws[128 * 8];
    __shared__ float bs[8];
    int t = threadIdx.x;
    for (int i = t; i < 1024; i += blockDim.x) ws[i] = Wa[i];
    if (t < 8) bs[t] = ba[t];
    __syncthreads();

    int idx = blockIdx.x * blockDim.x + t;
    int row = idx >> 3, c = idx & 7;
    if (row >= N) return;

    const float4* xr = (const float4*)(xa + (size_t)row * 128);
    float acc = bs[c];
#pragma unroll 8
    for (int kk = 0; kk < 32; kk++) {
        float4 a = xr[kk];
        int k = kk * 4;
        acc += a.x * ws[(k + 0) * 8 + c];
        acc += a.y * ws[(k + 1) * 8 + c];
        acc += a.z * ws[(k + 2) * 8 + c];
        acc += a.w * ws[(k + 3) * 8 + c];
    }
    out[(size_t)row * OUT_COLS + 256 + c] = acc;
}

// ---------------------------------------------------------------------------
// Per-edge: scores = relu(Pn[src] + Pa[dst]) @ W2 + b2 -> out[dst, slot*8 .. +8]
__global__ __launch_bounds__(256) void edge_kernel(
    const float* __restrict__ W2, const float* __restrict__ b2,
    const void* __restrict__ esrc, const void* __restrict__ edst,
    const void* __restrict__ eslot,
    float* __restrict__ out, int E)
{
    __shared__ float w2s[128 * 8];
    __shared__ float b2s[8];
    int t = threadIdx.x;
    for (int i = t; i < 1024; i += 256) w2s[i] = W2[i];
    if (t < 8) b2s[t] = b2[t];
    __syncthreads();

    int e = blockIdx.x * 256 + t;
    if (e >= E) return;

    long long src, dst, slot;
    if (g_idx64) {
        src  = ((const long long*)esrc)[e];
        dst  = ((const long long*)edst)[e];
        slot = ((const long long*)eslot)[e];
    } else {
        src  = ((const int*)esrc)[e];
        dst  = ((const int*)edst)[e];
        slot = ((const int*)eslot)[e];
    }

    const float4* pn = (const float4*)(g_Pn + (size_t)src * 128);
    const float4* pa = (const float4*)(g_Pa + (size_t)dst * 128);

    float acc[8];
#pragma unroll
    for (int c = 0; c < 8; c++) acc[c] = b2s[c];

#pragma unroll 4
    for (int kk = 0; kk < 32; kk++) {
        float4 a = pn[kk];
        float4 b = pa[kk];
        float v[4] = { fmaxf(a.x + b.x, 0.f), fmaxf(a.y + b.y, 0.f),
                       fmaxf(a.z + b.z, 0.f), fmaxf(a.w + b.w, 0.f) };
        int k = kk * 4;
#pragma unroll
        for (int j = 0; j < 4; j++) {
            float4 wlo = *(const float4*)(w2s + (k + j) * 8);
            float4 whi = *(const float4*)(w2s + (k + j) * 8 + 4);
            acc[0] += v[j] * wlo.x; acc[1] += v[j] * wlo.y;
            acc[2] += v[j] * wlo.z; acc[3] += v[j] * wlo.w;
            acc[4] += v[j] * whi.x; acc[5] += v[j] * whi.y;
            acc[6] += v[j] * whi.z; acc[7] += v[j] * whi.w;
        }
    }

    float* o = out + (size_t)dst * OUT_COLS + slot * 8;
    *(float4*)o       = make_float4(acc[0], acc[1], acc[2], acc[3]);
    *(float4*)(o + 4) = make_float4(acc[4], acc[5], acc[6], acc[7]);
}

// ---------------------------------------------------------------------------
extern "C" void kernel_launch(void* const* d_in, const int* in_sizes, int n_in,
                              void* d_out, int out_size)
{
    const float* x_nbr   = (const float*)d_in[0];
    const float* x_agent = (const float*)d_in[1];
    const float* W1      = (const float*)d_in[2];
    const float* b1      = (const float*)d_in[3];
    const float* W2      = (const float*)d_in[4];
    const float* b2      = (const float*)d_in[5];
    const float* Wa      = (const float*)d_in[6];
    const float* ba      = (const float*)d_in[7];
    const void*  esrc    = d_in[8];
    const void*  edst    = d_in[9];
    const void*  eslot   = d_in[10];

    int Nn = in_sizes[0] / F_IN;   // nbr node count
    int Na = in_sizes[1] / F_IN;   // agent node count
    int E  = in_sizes[8];          // edge count (element count, dtype-agnostic)
    float* out = (float*)d_out;

    const int gemm_smem = (128 * 128 + 64 * 132) * (int)sizeof(float); // 99328 B
    cudaFuncSetAttribute(gemm_x128, cudaFuncAttributeMaxDynamicSharedMemorySize,
                         gemm_smem);

    detect_idx_kernel<<<1, 1>>>((const int*)eslot);

    zero_out_kernel<<<512, 256>>>(out, out_size);

    gemm_x128<<<(Nn + 63) / 64, 256, gemm_smem>>>(x_nbr,   W1,             nullptr, 0, Nn);
    gemm_x128<<<(Na + 63) / 64, 256, gemm_smem>>>(x_agent, W1 + 128 * 128, b1,      1, Na);

    own_kernel<<<(Na * 8 + 255) / 256, 256>>>(x_agent, Wa, ba, out, Na);

    edge_kernel<<<(E + 255) / 256, 256>>>(W2, b2, esrc, edst, eslot, out, E);
}